// round 1
// baseline (speedup 1.0000x reference)
#include <cuda_runtime.h>
#include <math.h>

#define BATCH 256
#define NCHK  512
#define NVAR  1024
#define DCd   6
#define DVd   3
#define DD    16
#define EE    (NCHK*DCd)      /* 3072 */

#define IN_C  97
#define HID_C 388
#define OUT_C 96
#define IN_V  49
#define HID_V 196
#define OUT_V 49

// Persistent state buffers (allowed: __device__ globals, no cudaMalloc)
__device__ float g_Mc[(size_t)BATCH*EE*DD];   // 50.3 MB
__device__ float g_Mv[(size_t)BATCH*EE*DD];   // 50.3 MB

__device__ __forceinline__ float gelu_exact(float x){
    return 0.5f * x * (1.0f + erff(x * 0.7071067811865476f));
}

// ---------------------------------------------------------------------------
// Init: Mc0[b, perm[p], d] = (d==0) ? prior[p/DV] : 0   for all b,p,d
// ---------------------------------------------------------------------------
__global__ void init_kernel(const float* __restrict__ prior,
                            const int* __restrict__ perm)
{
    int idx = blockIdx.x * blockDim.x + threadIdx.x;
    if (idx >= BATCH*EE*DD) return;
    int d  = idx & (DD-1);
    int bp = idx >> 4;
    int p  = bp % EE;
    int b  = bp / EE;
    int j  = perm[p];                       // destination edge
    float v = (d == 0) ? prior[p / DVd] : 0.0f;
    g_Mc[((size_t)b*EE + j)*DD + d] = v;
}

// ---------------------------------------------------------------------------
// Check MLP: rows = B*NCHK (contiguous 96-float rows of g_Mc)
//   x(97) -> gelu(388) -> 96, then * sgn, write g_Mv (contiguous)
// 16 rows per block, 128 threads.
// ---------------------------------------------------------------------------
__global__ __launch_bounds__(128)
void check_kernel(const int* __restrict__ synd,
                  const float* __restrict__ W1, const float* __restrict__ b1,
                  const float* __restrict__ W2, const float* __restrict__ b2)
{
    __shared__ float xs[16*IN_C];     // 6.2 KB
    __shared__ float hs[16*HID_C];    // 24.8 KB

    const int tid = threadIdx.x;
    const long base_row = (long)blockIdx.x * 16;        // row = b*NCHK + chk

    // Load 16 contiguous 96-float rows of Mc
    const float* src = g_Mc + base_row * 96;
    for (int i = tid; i < 16*96; i += 128) {
        int r = i / 96, k = i - r*96;
        xs[r*IN_C + k] = src[i];
    }
    if (tid < 16) {
        int g = (int)(base_row + tid);
        xs[tid*IN_C + 96] = 1.0f - 2.0f * (float)synd[g];
    }
    __syncthreads();

    // ---- Layer 1: 97 -> 388, cols j = tid + 128*c ----
    float acc[4][16];
    #pragma unroll
    for (int c = 0; c < 4; c++)
        #pragma unroll
        for (int r = 0; r < 16; r++) acc[c][r] = 0.0f;

    #pragma unroll 4
    for (int k = 0; k < IN_C; k++) {
        const float* wrow = W1 + (size_t)k*HID_C;
        float w0 = wrow[tid];
        float w1_ = wrow[tid + 128];
        float w2_ = wrow[tid + 256];
        float w3_ = (tid < HID_C - 384) ? wrow[tid + 384] : 0.0f;
        #pragma unroll
        for (int r = 0; r < 16; r++) {
            float x = xs[r*IN_C + k];
            acc[0][r] = fmaf(x, w0,  acc[0][r]);
            acc[1][r] = fmaf(x, w1_, acc[1][r]);
            acc[2][r] = fmaf(x, w2_, acc[2][r]);
            acc[3][r] = fmaf(x, w3_, acc[3][r]);
        }
    }
    #pragma unroll
    for (int c = 0; c < 4; c++) {
        int j = tid + c*128;
        if (j < HID_C) {
            float bb = b1[j];
            #pragma unroll
            for (int r = 0; r < 16; r++)
                hs[r*HID_C + j] = gelu_exact(acc[c][r] + bb);
        }
    }
    __syncthreads();

    // ---- Layer 2: 388 -> 96. warp rg=tid/32 owns rows rg*4..rg*4+3,
    //      lane ct=tid%32 owns cols 3*ct..3*ct+2 ----
    const int rg = tid >> 5, ct = tid & 31;
    float acc2[4][3];
    #pragma unroll
    for (int rr = 0; rr < 4; rr++)
        #pragma unroll
        for (int c = 0; c < 3; c++) acc2[rr][c] = 0.0f;

    #pragma unroll 4
    for (int k = 0; k < HID_C; k++) {
        const float* wrow = W2 + (size_t)k*OUT_C + ct*3;
        float w0 = wrow[0], w1_ = wrow[1], w2_ = wrow[2];
        #pragma unroll
        for (int rr = 0; rr < 4; rr++) {
            float h = hs[(rg*4 + rr)*HID_C + k];
            acc2[rr][0] = fmaf(h, w0,  acc2[rr][0]);
            acc2[rr][1] = fmaf(h, w1_, acc2[rr][1]);
            acc2[rr][2] = fmaf(h, w2_, acc2[rr][2]);
        }
    }

    #pragma unroll
    for (int rr = 0; rr < 4; rr++) {
        int r = rg*4 + rr;
        float sg = xs[r*IN_C + 96];
        long row = base_row + r;
        #pragma unroll
        for (int c = 0; c < 3; c++) {
            int j = ct*3 + c;
            g_Mv[row*96 + j] = (acc2[rr][c] + b2[j]) * sg;
        }
    }
}

// ---------------------------------------------------------------------------
// Var MLP: rows = B*NVAR. Gather via perm, x(49)->gelu(196)->49,
//   cols 0..47 scattered back to g_Mc via perm, col 48 -> llr output.
// ---------------------------------------------------------------------------
__global__ __launch_bounds__(128)
void var_kernel(const int* __restrict__ perm,
                const float* __restrict__ prior,
                const float* __restrict__ W1, const float* __restrict__ b1,
                const float* __restrict__ W2, const float* __restrict__ b2,
                float* __restrict__ out_llr)   // pre-offset for iteration t
{
    __shared__ float xs[16*IN_V];     // 3.1 KB
    __shared__ float hs[16*HID_V];    // 12.5 KB

    const int tid = threadIdx.x;
    const long base_row = (long)blockIdx.x * 16;        // row = b*NVAR + v

    // Gather: xs[r][e*16+d] = Mv[b, perm[v*3+e], d]
    for (int i = tid; i < 16*48; i += 128) {
        int r = i / 48, q = i - r*48;
        int e = q >> 4, d = q & 15;
        long row = base_row + r;
        int b = (int)(row >> 10);
        int v = (int)(row & 1023);
        int p = perm[v*DVd + e];
        xs[r*IN_V + q] = g_Mv[((size_t)b*EE + p)*DD + d];
    }
    if (tid < 16) {
        long row = base_row + tid;
        xs[tid*IN_V + 48] = prior[row & 1023];
    }
    __syncthreads();

    // ---- Layer 1: 49 -> 196, cols j = tid (+128 for tid<68) ----
    float acc[2][16];
    #pragma unroll
    for (int c = 0; c < 2; c++)
        #pragma unroll
        for (int r = 0; r < 16; r++) acc[c][r] = 0.0f;

    const bool has_c1 = (tid < HID_V - 128);
    #pragma unroll 7
    for (int k = 0; k < IN_V; k++) {
        const float* wrow = W1 + (size_t)k*HID_V;
        float w0 = wrow[tid];
        float w1_ = has_c1 ? wrow[tid + 128] : 0.0f;
        #pragma unroll
        for (int r = 0; r < 16; r++) {
            float x = xs[r*IN_V + k];
            acc[0][r] = fmaf(x, w0,  acc[0][r]);
            acc[1][r] = fmaf(x, w1_, acc[1][r]);
        }
    }
    {
        float bb0 = b1[tid];
        #pragma unroll
        for (int r = 0; r < 16; r++)
            hs[r*HID_V + tid] = gelu_exact(acc[0][r] + bb0);
        if (has_c1) {
            float bb1 = b1[tid + 128];
            #pragma unroll
            for (int r = 0; r < 16; r++)
                hs[r*HID_V + tid + 128] = gelu_exact(acc[1][r] + bb1);
        }
    }
    __syncthreads();

    // ---- Layer 2: 196 -> 49. warp rg owns rows rg*4.., lane ct cols 2ct,2ct+1 ----
    const int rg = tid >> 5, ct = tid & 31;
    const int j0 = ct*2, j1 = ct*2 + 1;
    const bool p0 = (j0 < OUT_V), p1 = (j1 < OUT_V);

    float acc2[4][2];
    #pragma unroll
    for (int rr = 0; rr < 4; rr++) { acc2[rr][0] = 0.0f; acc2[rr][1] = 0.0f; }

    #pragma unroll 4
    for (int k = 0; k < HID_V; k++) {
        const float* wrow = W2 + (size_t)k*OUT_V;
        float w0 = p0 ? wrow[j0] : 0.0f;
        float w1_ = p1 ? wrow[j1] : 0.0f;
        #pragma unroll
        for (int rr = 0; rr < 4; rr++) {
            float h = hs[(rg*4 + rr)*HID_V + k];
            acc2[rr][0] = fmaf(h, w0,  acc2[rr][0]);
            acc2[rr][1] = fmaf(h, w1_, acc2[rr][1]);
        }
    }

    #pragma unroll
    for (int rr = 0; rr < 4; rr++) {
        long row = base_row + rg*4 + rr;
        int b = (int)(row >> 10);
        int v = (int)(row & 1023);
        #pragma unroll
        for (int c = 0; c < 2; c++) {
            int j = ct*2 + c;
            if (j >= OUT_V) continue;
            float y = acc2[rr][c] + b2[j];
            if (j < DVd*DD) {
                int e = j >> 4, d = j & 15;
                int p = perm[v*DVd + e];
                g_Mc[((size_t)b*EE + p)*DD + d] = y;
            } else {
                out_llr[row] = y;    // j == 48: llr for (b, v)
            }
        }
    }
}

// ---------------------------------------------------------------------------
extern "C" void kernel_launch(void* const* d_in, const int* in_sizes, int n_in,
                              void* d_out, int out_size)
{
    const int*   synd  = (const int*)  d_in[0];
    // d_in[1] = num_iters (derived from out_size instead; graph-capture-safe)
    const float* prior = (const float*)d_in[2];
    const int*   perm  = (const int*)  d_in[3];
    const float* cW1   = (const float*)d_in[4];
    const float* cb1   = (const float*)d_in[5];
    const float* cW2   = (const float*)d_in[6];
    const float* cb2   = (const float*)d_in[7];
    const float* vW1   = (const float*)d_in[8];
    const float* vb1   = (const float*)d_in[9];
    const float* vW2   = (const float*)d_in[10];
    const float* vb2   = (const float*)d_in[11];
    float* out = (float*)d_out;

    const int T = out_size / (BATCH * NVAR);

    init_kernel<<<(BATCH*EE*DD + 255)/256, 256>>>(prior, perm);

    const int check_blocks = (BATCH*NCHK) / 16;   // 8192
    const int var_blocks   = (BATCH*NVAR) / 16;   // 16384

    for (int t = 0; t < T; t++) {
        check_kernel<<<check_blocks, 128>>>(synd, cW1, cb1, cW2, cb2);
        var_kernel<<<var_blocks, 128>>>(perm, prior, vW1, vb1, vW2, vb2,
                                        out + (size_t)t * BATCH * NVAR);
    }
}

// round 2
// speedup vs baseline: 2.1019x; 2.1019x over previous
#include <cuda_runtime.h>
#include <math.h>

#define BATCH 256
#define NCHK  512
#define NVAR  1024
#define DVd   3
#define DD    16
#define EE    3072

#define C_IN   97
#define C_HID  388
#define C_OUT  96
#define V_IN   49
#define V_HID  196
#define V_OUT  49

// Persistent message buffers
__device__ float g_Mc[(size_t)BATCH*EE*DD];   // 50.3 MB
__device__ float g_Mv[(size_t)BATCH*EE*DD];   // 50.3 MB

__device__ __forceinline__ float gelu_exact(float x){
    return 0.5f * x * (1.0f + erff(x * 0.7071067811865476f));
}
__device__ __forceinline__ unsigned f2tf32(float x){
    unsigned r; asm("cvt.rn.tf32.f32 %0, %1;" : "=r"(r) : "f"(x)); return r;
}
__device__ __forceinline__ void mma_tf32(float* d, const unsigned* a, const unsigned* b){
    asm volatile("mma.sync.aligned.m16n8k8.row.col.f32.tf32.tf32.f32 "
        "{%0,%1,%2,%3},{%4,%5,%6,%7},{%8,%9},{%0,%1,%2,%3};"
        : "+f"(d[0]),"+f"(d[1]),"+f"(d[2]),"+f"(d[3])
        : "r"(a[0]),"r"(a[1]),"r"(a[2]),"r"(a[3]), "r"(b[0]),"r"(b[1]));
}

// ---------------------------------------------------------------------------
__global__ void init_kernel(const float* __restrict__ prior,
                            const int* __restrict__ perm)
{
    int idx = blockIdx.x * blockDim.x + threadIdx.x;
    if (idx >= BATCH*EE*DD) return;
    int d  = idx & (DD-1);
    int bp = idx >> 4;
    int p  = bp % EE;
    int b  = bp / EE;
    int j  = perm[p];
    float v = (d == 0) ? prior[p / DVd] : 0.0f;
    g_Mc[((size_t)b*EE + j)*DD + d] = v;
}

// ---------------------------------------------------------------------------
// CHECK: rows = B*NCHK = 131072. x(96+sgn) -> gelu(388) -> 96 -> *sgn -> g_Mv
// CTA: 256 threads (8 warps), 128 rows. Hidden chunked by 56 (7 chunks).
// SMEM strides: 108 (K1 pad), 60 (chunk pad)  — both ≡ 4 mod 8 (conflict-free).
// ---------------------------------------------------------------------------
#define CK1   104           /* 13 k-tiles */
#define CXS   108           /* xs row stride */
#define CWS   108           /* ws1 k stride */
#define CHS   60            /* h / ws2 k stride */

__global__ __launch_bounds__(256, 1)
void check_kernel(const int* __restrict__ synd,
                  const float* __restrict__ W1, const float* __restrict__ B1,
                  const float* __restrict__ W2, const float* __restrict__ B2)
{
    extern __shared__ char smem[];
    unsigned* us_x  = (unsigned*)smem;                        // 128*108
    unsigned* us_w1 = us_x  + 128*CXS;                        // 56*108
    unsigned* us_w2 = us_w1 + 56*CWS;                         // 96*60
    unsigned* us_h  = us_w2 + 96*CHS;                         // 8*16*60
    float*    ss    = (float*)(us_h + 8*16*CHS);              // 128 sgn

    const int tid  = threadIdx.x;
    const int warp = tid >> 5, lane = tid & 31;
    const int gid  = lane >> 2, tig = lane & 3;
    const int m0   = warp * 16;
    const long base_row = (long)blockIdx.x * 128;

    // ---- stage X (tf32 bits) ----
    const float4* src4 = (const float4*)(g_Mc + base_row * 96);
    for (int i = tid; i < 128*24; i += 256) {
        float4 v = src4[i];
        int r = i / 24, c4 = (i % 24) * 4;
        unsigned* p = us_x + r*CXS + c4;
        p[0]=f2tf32(v.x); p[1]=f2tf32(v.y); p[2]=f2tf32(v.z); p[3]=f2tf32(v.w);
    }
    if (tid < 128) {
        float sg = 1.0f - 2.0f * (float)synd[base_row + tid];
        ss[tid] = sg;
        us_x[tid*CXS + 96] = f2tf32(sg);
    }
    for (int i = tid; i < 128*11; i += 256) {
        int r = i / 11, c = 97 + i % 11;
        us_x[r*CXS + c] = 0u;
    }

    float acc2[12][4];
    #pragma unroll
    for (int n = 0; n < 12; n++)
        #pragma unroll
        for (int i = 0; i < 4; i++) acc2[n][i] = 0.0f;

    for (int cc = 0; cc < 7; cc++) {
        __syncthreads();
        // stage W1 slab: [n 56][k 108], tf32, zero-padded
        for (int i = tid; i < 56*CWS; i += 256) {
            int k = i / 56, n = i % 56;
            int col = cc*56 + n;
            float v = (k < C_IN && col < C_HID) ? W1[(size_t)k*C_HID + col] : 0.0f;
            us_w1[n*CWS + k] = f2tf32(v);
        }
        // stage W2 slab: [n 96][k 60]
        for (int i = tid; i < CHS*96; i += 256) {
            int k = i / 96, n = i % 96;
            int hrow = cc*56 + k;
            float v = (k < 56 && hrow < C_HID) ? W2[(size_t)hrow*C_OUT + n] : 0.0f;
            us_w2[n*CHS + k] = f2tf32(v);
        }
        __syncthreads();

        // ---- layer 1: m16 x n56, K=104 ----
        float acc1[7][4];
        #pragma unroll
        for (int n = 0; n < 7; n++)
            #pragma unroll
            for (int i = 0; i < 4; i++) acc1[n][i] = 0.0f;

        #pragma unroll
        for (int kt = 0; kt < 13; kt++) {
            unsigned a[4];
            const unsigned* xa = us_x + (m0 + gid)*CXS + kt*8 + tig;
            a[0] = xa[0]; a[1] = xa[8*CXS]; a[2] = xa[4]; a[3] = xa[8*CXS + 4];
            #pragma unroll
            for (int nt = 0; nt < 7; nt++) {
                unsigned b[2];
                const unsigned* wb = us_w1 + (nt*8 + gid)*CWS + kt*8 + tig;
                b[0] = wb[0]; b[1] = wb[4];
                mma_tf32(acc1[nt], a, b);
            }
        }

        // ---- bias + gelu -> per-warp H chunk (tf32 bits) ----
        unsigned* uh = us_h + warp*16*CHS;
        #pragma unroll
        for (int nt = 0; nt < 7; nt++) {
            #pragma unroll
            for (int i = 0; i < 4; i++) {
                int row  = gid + ((i >> 1) << 3);
                int colL = nt*8 + 2*tig + (i & 1);
                int gcol = cc*56 + colL;
                float h = 0.0f;
                if (gcol < C_HID) h = gelu_exact(acc1[nt][i] + B1[gcol]);
                uh[row*CHS + colL] = f2tf32(h);
            }
        }
        __syncwarp();

        // ---- layer 2 partial: K=56 over this chunk ----
        #pragma unroll
        for (int kt = 0; kt < 7; kt++) {
            unsigned a[4];
            const unsigned* ha = uh + gid*CHS + kt*8 + tig;
            a[0] = ha[0]; a[1] = ha[8*CHS]; a[2] = ha[4]; a[3] = ha[8*CHS + 4];
            #pragma unroll
            for (int nt = 0; nt < 12; nt++) {
                unsigned b[2];
                const unsigned* wb = us_w2 + (nt*8 + gid)*CHS + kt*8 + tig;
                b[0] = wb[0]; b[1] = wb[4];
                mma_tf32(acc2[nt], a, b);
            }
        }
    }

    // ---- epilogue: bias, *sgn, store Mv ----
    #pragma unroll
    for (int nt = 0; nt < 12; nt++) {
        int col = nt*8 + 2*tig;
        float bb0 = B2[col], bb1 = B2[col+1];
        #pragma unroll
        for (int half = 0; half < 2; half++) {
            int rloc = m0 + gid + half*8;
            float sg = ss[rloc];
            long grow = base_row + rloc;
            float2 y;
            y.x = (acc2[nt][half*2+0] + bb0) * sg;
            y.y = (acc2[nt][half*2+1] + bb1) * sg;
            *(float2*)(g_Mv + (size_t)grow*96 + col) = y;
        }
    }
}

// ---------------------------------------------------------------------------
// VAR: rows = B*NVAR = 262144. gather(48)+prior -> gelu(196) -> 49
//   cols 0..47 scattered via perm to g_Mc, col 48 -> llr.
// CTA: 256 threads, 128 rows. Hidden chunked by 56 (4 chunks). strides = 60.
// ---------------------------------------------------------------------------
#define VST 60

__global__ __launch_bounds__(256, 2)
void var_kernel(const int* __restrict__ perm,
                const float* __restrict__ prior,
                const float* __restrict__ W1, const float* __restrict__ B1,
                const float* __restrict__ W2, const float* __restrict__ B2,
                float* __restrict__ out_llr)
{
    extern __shared__ char smem[];
    unsigned* us_x  = (unsigned*)smem;                        // 128*60
    unsigned* us_w1 = us_x  + 128*VST;                        // 56*60
    unsigned* us_w2 = us_w1 + 56*VST;                         // 56*60
    unsigned* us_h  = us_w2 + 56*VST;                         // 8*16*60

    const int tid  = threadIdx.x;
    const int warp = tid >> 5, lane = tid & 31;
    const int gid  = lane >> 2, tig = lane & 3;
    const int m0   = warp * 16;
    const long base_row = (long)blockIdx.x * 128;

    // ---- gather X via perm ----
    for (int i = tid; i < 128*12; i += 256) {
        int r = i / 12, j = i % 12;
        int e = j >> 2, c4 = (j & 3) * 4;
        long row = base_row + r;
        int b = (int)(row >> 10), v = (int)(row & 1023);
        int p = perm[v*DVd + e];
        float4 val = *(const float4*)(g_Mv + ((size_t)b*EE + p)*DD + c4);
        unsigned* q = us_x + r*VST + e*16 + c4;
        q[0]=f2tf32(val.x); q[1]=f2tf32(val.y); q[2]=f2tf32(val.z); q[3]=f2tf32(val.w);
    }
    if (tid < 128) {
        long row = base_row + tid;
        us_x[tid*VST + 48] = f2tf32(prior[row & 1023]);
    }
    for (int i = tid; i < 128*7; i += 256) {
        int r = i / 7, c = 49 + i % 7;
        us_x[r*VST + c] = 0u;
    }

    float acc2[7][4];
    #pragma unroll
    for (int n = 0; n < 7; n++)
        #pragma unroll
        for (int i = 0; i < 4; i++) acc2[n][i] = 0.0f;

    for (int cc = 0; cc < 4; cc++) {
        __syncthreads();
        for (int i = tid; i < VST*56; i += 256) {
            int k = i / 56, n = i % 56;
            int col = cc*56 + n;
            float v = (k < V_IN && col < V_HID) ? W1[(size_t)k*V_HID + col] : 0.0f;
            us_w1[n*VST + k] = f2tf32(v);
        }
        for (int i = tid; i < VST*56; i += 256) {
            int k = i / 56, n = i % 56;
            int hrow = cc*56 + k;
            float v = (k < 56 && hrow < V_HID && n < V_OUT)
                      ? W2[(size_t)hrow*V_OUT + n] : 0.0f;
            us_w2[n*VST + k] = f2tf32(v);
        }
        __syncthreads();

        // ---- layer 1: m16 x n56, K=56 ----
        float acc1[7][4];
        #pragma unroll
        for (int n = 0; n < 7; n++)
            #pragma unroll
            for (int i = 0; i < 4; i++) acc1[n][i] = 0.0f;

        #pragma unroll
        for (int kt = 0; kt < 7; kt++) {
            unsigned a[4];
            const unsigned* xa = us_x + (m0 + gid)*VST + kt*8 + tig;
            a[0] = xa[0]; a[1] = xa[8*VST]; a[2] = xa[4]; a[3] = xa[8*VST + 4];
            #pragma unroll
            for (int nt = 0; nt < 7; nt++) {
                unsigned b[2];
                const unsigned* wb = us_w1 + (nt*8 + gid)*VST + kt*8 + tig;
                b[0] = wb[0]; b[1] = wb[4];
                mma_tf32(acc1[nt], a, b);
            }
        }

        unsigned* uh = us_h + warp*16*VST;
        #pragma unroll
        for (int nt = 0; nt < 7; nt++) {
            #pragma unroll
            for (int i = 0; i < 4; i++) {
                int row  = gid + ((i >> 1) << 3);
                int colL = nt*8 + 2*tig + (i & 1);
                int gcol = cc*56 + colL;
                float h = 0.0f;
                if (gcol < V_HID) h = gelu_exact(acc1[nt][i] + B1[gcol]);
                uh[row*VST + colL] = f2tf32(h);
            }
        }
        __syncwarp();

        #pragma unroll
        for (int kt = 0; kt < 7; kt++) {
            unsigned a[4];
            const unsigned* ha = uh + gid*VST + kt*8 + tig;
            a[0] = ha[0]; a[1] = ha[8*VST]; a[2] = ha[4]; a[3] = ha[8*VST + 4];
            #pragma unroll
            for (int nt = 0; nt < 7; nt++) {
                unsigned b[2];
                const unsigned* wb = us_w2 + (nt*8 + gid)*VST + kt*8 + tig;
                b[0] = wb[0]; b[1] = wb[4];
                mma_tf32(acc2[nt], a, b);
            }
        }
    }

    // ---- epilogue: scatter to g_Mc (cols<48), llr (col 48) ----
    #pragma unroll
    for (int nt = 0; nt < 7; nt++) {
        #pragma unroll
        for (int i = 0; i < 4; i++) {
            int col = nt*8 + 2*tig + (i & 1);
            if (col > 48) continue;
            int rloc = m0 + gid + ((i >> 1) << 3);
            long grow = base_row + rloc;
            int b = (int)(grow >> 10), v = (int)(grow & 1023);
            float y = acc2[nt][i] + B2[col];
            if (col < 48) {
                int e = col >> 4, d = col & 15;
                int p = perm[v*DVd + e];
                g_Mc[((size_t)b*EE + p)*DD + d] = y;
            } else {
                out_llr[grow] = y;
            }
        }
    }
}

// ---------------------------------------------------------------------------
extern "C" void kernel_launch(void* const* d_in, const int* in_sizes, int n_in,
                              void* d_out, int out_size)
{
    const int*   synd  = (const int*)  d_in[0];
    const float* prior = (const float*)d_in[2];
    const int*   perm  = (const int*)  d_in[3];
    const float* cW1   = (const float*)d_in[4];
    const float* cb1   = (const float*)d_in[5];
    const float* cW2   = (const float*)d_in[6];
    const float* cb2   = (const float*)d_in[7];
    const float* vW1   = (const float*)d_in[8];
    const float* vb1   = (const float*)d_in[9];
    const float* vW2   = (const float*)d_in[10];
    const float* vb2   = (const float*)d_in[11];
    float* out = (float*)d_out;

    const int T = out_size / (BATCH * NVAR);

    const int check_smem = (128*CXS + 56*CWS + 96*CHS + 8*16*CHS) * 4 + 128*4;
    const int var_smem   = (128*VST + 56*VST + 56*VST + 8*16*VST) * 4;

    static int configured = 0;
    cudaFuncSetAttribute(check_kernel, cudaFuncAttributeMaxDynamicSharedMemorySize, check_smem);
    cudaFuncSetAttribute(var_kernel,   cudaFuncAttributeMaxDynamicSharedMemorySize, var_smem);
    (void)configured;

    init_kernel<<<(BATCH*EE*DD + 255)/256, 256>>>(prior, perm);

    const int check_blocks = (BATCH*NCHK) / 128;   // 1024
    const int var_blocks   = (BATCH*NVAR) / 128;   // 2048

    for (int t = 0; t < T; t++) {
        check_kernel<<<check_blocks, 256, check_smem>>>(synd, cW1, cb1, cW2, cb2);
        var_kernel<<<var_blocks, 256, var_smem>>>(perm, prior, vW1, vb1, vW2, vb2,
                                                  out + (size_t)t * BATCH * NVAR);
    }
}

// round 3
// speedup vs baseline: 3.5504x; 1.6892x over previous
#include <cuda_runtime.h>
#include <math.h>

#define BATCH 256
#define NCHK  512
#define NVAR  1024
#define DVd   3
#define DD    16
#define EE    3072

#define C_IN   97
#define C_HID  388
#define C_OUT  96
#define V_IN   49
#define V_HID  196
#define V_OUT  49

// Persistent message buffers
__device__ float g_Mc[(size_t)BATCH*EE*DD];   // 50.3 MB
__device__ float g_Mv[(size_t)BATCH*EE*DD];   // 50.3 MB

// Fragment-ordered tf32 weight buffers (filled once per launch by prep kernels)
// check W1: [cc7][nt7][kt12][lane32][2]
__device__ unsigned g_cW1f[7*7*12*64];        // 37632
// check W2: [cc7][nt12][ktl7][lane32][2]
__device__ unsigned g_cW2f[7*12*7*64];        // 37632
// var W1:  [cc4][nt7][kt6][lane32][2]
__device__ unsigned g_vW1f[4*7*6*64];         // 10752
// var W2:  [cc4][nt7][ktl7][lane32][2]
__device__ unsigned g_vW2f[4*7*7*64];         // 12544

__device__ __forceinline__ float gelu_exact(float x){
    return 0.5f * x * (1.0f + erff(x * 0.7071067811865476f));
}
__device__ __forceinline__ unsigned f2tf32(float x){
    unsigned r; asm("cvt.rn.tf32.f32 %0, %1;" : "=r"(r) : "f"(x)); return r;
}
__device__ __forceinline__ void mma_tf32(float* d, const unsigned* a, unsigned b0, unsigned b1){
    asm volatile("mma.sync.aligned.m16n8k8.row.col.f32.tf32.tf32.f32 "
        "{%0,%1,%2,%3},{%4,%5,%6,%7},{%8,%9},{%0,%1,%2,%3};"
        : "+f"(d[0]),"+f"(d[1]),"+f"(d[2]),"+f"(d[3])
        : "r"(a[0]),"r"(a[1]),"r"(a[2]),"r"(a[3]), "r"(b0),"r"(b1));
}

// ---------------------------------------------------------------------------
__global__ void init_kernel(const float* __restrict__ prior,
                            const int* __restrict__ perm)
{
    int idx = blockIdx.x * blockDim.x + threadIdx.x;
    if (idx >= BATCH*EE*DD) return;
    int d  = idx & (DD-1);
    int bp = idx >> 4;
    int p  = bp % EE;
    int b  = bp / EE;
    int j  = perm[p];
    float v = (d == 0) ? prior[p / DVd] : 0.0f;
    g_Mc[((size_t)b*EE + j)*DD + d] = v;
}

// ---------------------------------------------------------------------------
__global__ void prep_check(const float* __restrict__ W1, const float* __restrict__ W2)
{
    int idx = blockIdx.x*blockDim.x + threadIdx.x;
    if (idx < 37632) {
        int s = idx & 1, l = (idx >> 1) & 31;
        int r = idx >> 6;
        int kt = r % 12; r /= 12;
        int nt = r % 7;  int cc = r / 7;
        int gid = l >> 2, tig = l & 3;
        int k = kt*8 + tig + 4*s;                 // < 96
        int n = cc*56 + nt*8 + gid;
        float v = (n < C_HID) ? W1[k*C_HID + n] : 0.0f;
        g_cW1f[idx] = f2tf32(v);
    } else if (idx < 75264) {
        int j = idx - 37632;
        int s = j & 1, l = (j >> 1) & 31;
        int r = j >> 6;
        int ktl = r % 7; r /= 7;
        int nt = r % 12; int cc = r / 12;
        int gid = l >> 2, tig = l & 3;
        int k = cc*56 + ktl*8 + tig + 4*s;
        int n = nt*8 + gid;                       // < 96
        float v = (k < C_HID) ? W2[k*C_OUT + n] : 0.0f;
        g_cW2f[j] = f2tf32(v);
    }
}

__global__ void prep_var(const float* __restrict__ W1, const float* __restrict__ W2)
{
    int idx = blockIdx.x*blockDim.x + threadIdx.x;
    if (idx < 10752) {
        int s = idx & 1, l = (idx >> 1) & 31;
        int r = idx >> 6;
        int kt = r % 6; r /= 6;
        int nt = r % 7; int cc = r / 7;
        int gid = l >> 2, tig = l & 3;
        int k = kt*8 + tig + 4*s;                 // < 48
        int n = cc*56 + nt*8 + gid;
        float v = (n < V_HID) ? W1[k*V_HID + n] : 0.0f;
        g_vW1f[idx] = f2tf32(v);
    } else if (idx < 23296) {
        int j = idx - 10752;
        int s = j & 1, l = (j >> 1) & 31;
        int r = j >> 6;
        int ktl = r % 7; r /= 7;
        int nt = r % 7; int cc = r / 7;
        int gid = l >> 2, tig = l & 3;
        int k = cc*56 + ktl*8 + tig + 4*s;
        int n = nt*8 + gid;
        float v = (k < V_HID && n < V_OUT) ? W2[k*V_OUT + n] : 0.0f;
        g_vW2f[j] = f2tf32(v);
    }
}

// ---------------------------------------------------------------------------
// CHECK: 131072 rows. X(96)+sgn -> gelu(388) -> 96 -> *sgn -> g_Mv.
// 256 threads, 128 rows/CTA. A-in-regs, rank-1 sgn, frag-ordered weights.
// ---------------------------------------------------------------------------
#define UHS 61

__global__ __launch_bounds__(256, 1)
void check_kernel(const int* __restrict__ synd,
                  const float* __restrict__ W1raw, const float* __restrict__ B1,
                  const float* __restrict__ B2)
{
    extern __shared__ unsigned smem[];
    unsigned* sw1 = smem;                 // 5376
    unsigned* sw2 = sw1 + 5376;           // 5376
    unsigned* uh  = sw2 + 5376;           // 8*16*61 = 7808
    float* sb1  = (float*)(uh + 8*16*UHS);  // 56
    float* sw1r = sb1 + 56;                  // 56
    float* sb2  = sw1r + 56;                 // 96

    const int tid  = threadIdx.x;
    const int warp = tid >> 5, lane = tid & 31;
    const int gid  = lane >> 2, tig = lane & 3;
    const int m0   = warp * 16;
    const int base_row = blockIdx.x * 128;
    const int r0 = base_row + m0 + gid, r1 = r0 + 8;

    if (tid < 96) sb2[tid] = B2[tid];

    // A fragments for all 12 k-tiles, in registers for the whole kernel
    unsigned A[12][4];
    {
        const float* x0 = g_Mc + (size_t)r0 * 96;
        const float* x1 = g_Mc + (size_t)r1 * 96;
        #pragma unroll
        for (int kt = 0; kt < 12; kt++) {
            int c0 = kt*8 + tig;
            A[kt][0] = f2tf32(x0[c0]);
            A[kt][1] = f2tf32(x1[c0]);
            A[kt][2] = f2tf32(x0[c0+4]);
            A[kt][3] = f2tf32(x1[c0+4]);
        }
    }
    const float sg0 = 1.0f - 2.0f * (float)synd[r0];
    const float sg1 = 1.0f - 2.0f * (float)synd[r1];

    float acc2[12][4];
    #pragma unroll
    for (int n = 0; n < 12; n++)
        #pragma unroll
        for (int i = 0; i < 4; i++) acc2[n][i] = 0.0f;

    unsigned* uhw = uh + warp*16*UHS;

    for (int cc = 0; cc < 7; cc++) {
        __syncthreads();
        // stage weight chunk: pure vectorized copy
        {
            const uint4* s1 = (const uint4*)(g_cW1f + cc*5376);
            const uint4* s2 = (const uint4*)(g_cW2f + cc*5376);
            uint4* d1 = (uint4*)sw1;
            uint4* d2 = (uint4*)sw2;
            #pragma unroll
            for (int i = tid; i < 1344; i += 256) { d1[i] = s1[i]; d2[i] = s2[i]; }
            if (tid < 56) {
                int gcol = cc*56 + tid;
                bool ok = gcol < C_HID;
                sb1[tid]  = ok ? B1[gcol] : 0.0f;
                sw1r[tid] = ok ? W1raw[96*C_HID + gcol] : 0.0f;
            }
        }
        __syncthreads();

        // layer 1: init with rank-1 sgn term, then 12 k-tiles
        float acc1[7][4];
        #pragma unroll
        for (int nt = 0; nt < 7; nt++) {
            #pragma unroll
            for (int i = 0; i < 4; i++) {
                int colloc = nt*8 + 2*tig + (i & 1);
                acc1[nt][i] = ((i >> 1) ? sg1 : sg0) * sw1r[colloc];
            }
        }
        #pragma unroll
        for (int kt = 0; kt < 12; kt++) {
            #pragma unroll
            for (int nt = 0; nt < 7; nt++) {
                uint2 b = *(const uint2*)(sw1 + ((nt*12 + kt)*32 + lane)*2);
                mma_tf32(acc1[nt], A[kt], b.x, b.y);
            }
        }

        // gelu -> per-warp H (tf32)
        #pragma unroll
        for (int nt = 0; nt < 7; nt++) {
            #pragma unroll
            for (int i = 0; i < 4; i++) {
                int rowloc = gid + ((i >> 1) << 3);
                int colloc = nt*8 + 2*tig + (i & 1);
                int gcol = cc*56 + colloc;
                float h = (gcol < C_HID) ? gelu_exact(acc1[nt][i] + sb1[colloc]) : 0.0f;
                uhw[rowloc*UHS + colloc] = f2tf32(h);
            }
        }
        __syncwarp();

        // layer 2 partial over this chunk
        #pragma unroll
        for (int ktl = 0; ktl < 7; ktl++) {
            unsigned a[4];
            a[0] = uhw[gid*UHS       + ktl*8 + tig];
            a[1] = uhw[(gid+8)*UHS   + ktl*8 + tig];
            a[2] = uhw[gid*UHS       + ktl*8 + tig + 4];
            a[3] = uhw[(gid+8)*UHS   + ktl*8 + tig + 4];
            #pragma unroll
            for (int nt = 0; nt < 12; nt++) {
                uint2 b = *(const uint2*)(sw2 + ((nt*7 + ktl)*32 + lane)*2);
                mma_tf32(acc2[nt], a, b.x, b.y);
            }
        }
        __syncwarp();
    }

    // epilogue
    #pragma unroll
    for (int nt = 0; nt < 12; nt++) {
        int col = nt*8 + 2*tig;
        float bb0 = sb2[col], bb1 = sb2[col+1];
        float2 y0, y1;
        y0.x = (acc2[nt][0] + bb0) * sg0;
        y0.y = (acc2[nt][1] + bb1) * sg0;
        y1.x = (acc2[nt][2] + bb0) * sg1;
        y1.y = (acc2[nt][3] + bb1) * sg1;
        *(float2*)(g_Mv + (size_t)r0*96 + col) = y0;
        *(float2*)(g_Mv + (size_t)r1*96 + col) = y1;
    }
}

// ---------------------------------------------------------------------------
// VAR: 262144 rows. gather(48)+prior -> gelu(196) -> 48 scatter + llr.
// 256 threads, 128 rows/CTA, occupancy 2.
// ---------------------------------------------------------------------------
__global__ __launch_bounds__(256, 2)
void var_kernel(const int* __restrict__ perm,
                const float* __restrict__ prior,
                const float* __restrict__ W1raw, const float* __restrict__ B1,
                const float* __restrict__ B2,
                float* __restrict__ out_llr)
{
    extern __shared__ unsigned smem[];
    unsigned* sw1 = smem;                 // 2688
    unsigned* sw2 = sw1 + 2688;           // 3136
    unsigned* uh  = sw2 + 3136;           // 8*16*61 = 7808
    float* sb1  = (float*)(uh + 8*16*UHS);  // 56
    float* sw1r = sb1 + 56;                  // 56
    float* sb2  = sw1r + 56;                 // 49

    const int tid  = threadIdx.x;
    const int warp = tid >> 5, lane = tid & 31;
    const int gid  = lane >> 2, tig = lane & 3;
    const int m0   = warp * 16;
    const int base_row = blockIdx.x * 128;
    const int r0 = base_row + m0 + gid, r1 = r0 + 8;
    const int b0i = r0 >> 10, v0 = r0 & 1023;
    const int b1i = r1 >> 10, v1 = r1 & 1023;

    if (tid < 49) sb2[tid] = B2[tid];

    int p0[3], p1[3];
    #pragma unroll
    for (int e = 0; e < 3; e++) {
        p0[e] = perm[v0*DVd + e];
        p1[e] = perm[v1*DVd + e];
    }
    const float pr0 = prior[v0], pr1 = prior[v1];

    // A fragments (6 k-tiles = 48 cols), in registers
    unsigned A[6][4];
    {
        const float* base0 = g_Mv + (size_t)b0i*EE*DD;
        const float* base1 = g_Mv + (size_t)b1i*EE*DD;
        #pragma unroll
        for (int kt = 0; kt < 6; kt++) {
            int e = kt >> 1;
            int d = ((kt & 1) << 3) + tig;
            A[kt][0] = f2tf32(base0[p0[e]*DD + d]);
            A[kt][1] = f2tf32(base1[p1[e]*DD + d]);
            A[kt][2] = f2tf32(base0[p0[e]*DD + d + 4]);
            A[kt][3] = f2tf32(base1[p1[e]*DD + d + 4]);
        }
    }

    float acc2[7][4];
    #pragma unroll
    for (int n = 0; n < 7; n++)
        #pragma unroll
        for (int i = 0; i < 4; i++) acc2[n][i] = 0.0f;

    unsigned* uhw = uh + warp*16*UHS;

    for (int cc = 0; cc < 4; cc++) {
        __syncthreads();
        {
            const uint4* s1 = (const uint4*)(g_vW1f + cc*2688);
            const uint4* s2 = (const uint4*)(g_vW2f + cc*3136);
            uint4* d1 = (uint4*)sw1;
            uint4* d2 = (uint4*)sw2;
            #pragma unroll
            for (int i = tid; i < 784; i += 256) {
                if (i < 672) d1[i] = s1[i];
                d2[i] = s2[i];
            }
            if (tid < 56) {
                int gcol = cc*56 + tid;
                bool ok = gcol < V_HID;
                sb1[tid]  = ok ? B1[gcol] : 0.0f;
                sw1r[tid] = ok ? W1raw[48*V_HID + gcol] : 0.0f;
            }
        }
        __syncthreads();

        float acc1[7][4];
        #pragma unroll
        for (int nt = 0; nt < 7; nt++) {
            #pragma unroll
            for (int i = 0; i < 4; i++) {
                int colloc = nt*8 + 2*tig + (i & 1);
                acc1[nt][i] = ((i >> 1) ? pr1 : pr0) * sw1r[colloc];
            }
        }
        #pragma unroll
        for (int kt = 0; kt < 6; kt++) {
            #pragma unroll
            for (int nt = 0; nt < 7; nt++) {
                uint2 b = *(const uint2*)(sw1 + ((nt*6 + kt)*32 + lane)*2);
                mma_tf32(acc1[nt], A[kt], b.x, b.y);
            }
        }

        #pragma unroll
        for (int nt = 0; nt < 7; nt++) {
            #pragma unroll
            for (int i = 0; i < 4; i++) {
                int rowloc = gid + ((i >> 1) << 3);
                int colloc = nt*8 + 2*tig + (i & 1);
                int gcol = cc*56 + colloc;
                float h = (gcol < V_HID) ? gelu_exact(acc1[nt][i] + sb1[colloc]) : 0.0f;
                uhw[rowloc*UHS + colloc] = f2tf32(h);
            }
        }
        __syncwarp();

        #pragma unroll
        for (int ktl = 0; ktl < 7; ktl++) {
            unsigned a[4];
            a[0] = uhw[gid*UHS     + ktl*8 + tig];
            a[1] = uhw[(gid+8)*UHS + ktl*8 + tig];
            a[2] = uhw[gid*UHS     + ktl*8 + tig + 4];
            a[3] = uhw[(gid+8)*UHS + ktl*8 + tig + 4];
            #pragma unroll
            for (int nt = 0; nt < 7; nt++) {
                uint2 b = *(const uint2*)(sw2 + ((nt*7 + ktl)*32 + lane)*2);
                mma_tf32(acc2[nt], a, b.x, b.y);
            }
        }
        __syncwarp();
    }

    // epilogue: scatter via the same perm regs
    #pragma unroll
    for (int nt = 0; nt < 7; nt++) {
        #pragma unroll
        for (int i = 0; i < 4; i++) {
            int col = nt*8 + 2*tig + (i & 1);
            if (col > 48) continue;
            int rowsel = i >> 1;
            float y = acc2[nt][i] + sb2[col];
            if (col < 48) {
                int e = col >> 4, d = col & 15;
                int p = rowsel ? p1[e] : p0[e];
                int b = rowsel ? b1i : b0i;
                g_Mc[((size_t)b*EE + p)*DD + d] = y;
            } else {
                out_llr[rowsel ? r1 : r0] = y;
            }
        }
    }
}

// ---------------------------------------------------------------------------
extern "C" void kernel_launch(void* const* d_in, const int* in_sizes, int n_in,
                              void* d_out, int out_size)
{
    const int*   synd  = (const int*)  d_in[0];
    const float* prior = (const float*)d_in[2];
    const int*   perm  = (const int*)  d_in[3];
    const float* cW1   = (const float*)d_in[4];
    const float* cb1   = (const float*)d_in[5];
    const float* cW2   = (const float*)d_in[6];
    const float* cb2   = (const float*)d_in[7];
    const float* vW1   = (const float*)d_in[8];
    const float* vb1   = (const float*)d_in[9];
    const float* vW2   = (const float*)d_in[10];
    const float* vb2   = (const float*)d_in[11];
    float* out = (float*)d_out;

    const int T = out_size / (BATCH * NVAR);

    const int check_smem = (5376 + 5376 + 8*16*UHS) * 4 + (56+56+96)*4;
    const int var_smem   = (2688 + 3136 + 8*16*UHS) * 4 + (56+56+49)*4;

    cudaFuncSetAttribute(check_kernel, cudaFuncAttributeMaxDynamicSharedMemorySize, check_smem);
    cudaFuncSetAttribute(var_kernel,   cudaFuncAttributeMaxDynamicSharedMemorySize, var_smem);

    init_kernel<<<(BATCH*EE*DD + 255)/256, 256>>>(prior, perm);
    prep_check<<<(75264 + 255)/256, 256>>>(cW1, cW2);
    prep_var<<<(23296 + 255)/256, 256>>>(vW1, vW2);

    const int check_blocks = (BATCH*NCHK) / 128;   // 1024
    const int var_blocks   = (BATCH*NVAR) / 128;   // 2048

    for (int t = 0; t < T; t++) {
        check_kernel<<<check_blocks, 256, check_smem>>>(synd, cW1, cb1, cb2);
        var_kernel<<<var_blocks, 256, var_smem>>>(perm, prior, vW1, vb1, vb2,
                                                  out + (size_t)t * BATCH * NVAR);
    }
}

// round 4
// speedup vs baseline: 3.5510x; 1.0001x over previous
#include <cuda_runtime.h>
#include <math.h>

#define BATCH 256
#define NCHK  512
#define NVAR  1024
#define DVd   3
#define DD    16
#define EE    3072

#define C_IN   97
#define C_HID  388
#define C_OUT  96
#define V_IN   49
#define V_HID  196
#define V_OUT  49

// Persistent message buffers
__device__ float g_Mc[(size_t)BATCH*EE*DD];   // 50.3 MB
__device__ float g_Mv[(size_t)BATCH*EE*DD];   // 50.3 MB

// Fragment-ordered tf32 weight buffers (filled once per launch by prep kernels)
// check W1: [cc7][nt7][kt12][lane32][2]
__device__ unsigned g_cW1f[7*7*12*64];        // 37632
// check W2: [cc7][nt12][ktl7][lane32][2]
__device__ unsigned g_cW2f[7*12*7*64];        // 37632
// var W1:  [cc4][nt7][kt6][lane32][2]
__device__ unsigned g_vW1f[4*7*6*64];         // 10752
// var W2:  [cc4][nt7][ktl7][lane32][2]
__device__ unsigned g_vW2f[4*7*7*64];         // 12544

__device__ __forceinline__ float gelu_exact(float x){
    return 0.5f * x * (1.0f + erff(x * 0.7071067811865476f));
}
__device__ __forceinline__ unsigned f2tf32(float x){
    unsigned r; asm("cvt.rn.tf32.f32 %0, %1;" : "=r"(r) : "f"(x)); return r;
}
__device__ __forceinline__ void mma_tf32(float* d, const unsigned* a, unsigned b0, unsigned b1){
    asm volatile("mma.sync.aligned.m16n8k8.row.col.f32.tf32.tf32.f32 "
        "{%0,%1,%2,%3},{%4,%5,%6,%7},{%8,%9},{%0,%1,%2,%3};"
        : "+f"(d[0]),"+f"(d[1]),"+f"(d[2]),"+f"(d[3])
        : "r"(a[0]),"r"(a[1]),"r"(a[2]),"r"(a[3]), "r"(b0),"r"(b1));
}

// ---------------------------------------------------------------------------
__global__ void init_kernel(const float* __restrict__ prior,
                            const int* __restrict__ perm)
{
    int idx = blockIdx.x * blockDim.x + threadIdx.x;
    if (idx >= BATCH*EE*DD) return;
    int d  = idx & (DD-1);
    int bp = idx >> 4;
    int p  = bp % EE;
    int b  = bp / EE;
    int j  = perm[p];
    float v = (d == 0) ? prior[p / DVd] : 0.0f;
    g_Mc[((size_t)b*EE + j)*DD + d] = v;
}

// ---------------------------------------------------------------------------
__global__ void prep_check(const float* __restrict__ W1, const float* __restrict__ W2)
{
    int idx = blockIdx.x*blockDim.x + threadIdx.x;
    if (idx < 37632) {
        int s = idx & 1, l = (idx >> 1) & 31;
        int r = idx >> 6;
        int kt = r % 12; r /= 12;
        int nt = r % 7;  int cc = r / 7;
        int gid = l >> 2, tig = l & 3;
        int k = kt*8 + tig + 4*s;                 // < 96
        int n = cc*56 + nt*8 + gid;
        float v = (n < C_HID) ? W1[k*C_HID + n] : 0.0f;
        g_cW1f[idx] = f2tf32(v);
    } else if (idx < 75264) {
        int j = idx - 37632;
        int s = j & 1, l = (j >> 1) & 31;
        int r = j >> 6;
        int ktl = r % 7; r /= 7;
        int nt = r % 12; int cc = r / 12;
        int gid = l >> 2, tig = l & 3;
        int k = cc*56 + ktl*8 + tig + 4*s;
        int n = nt*8 + gid;                       // < 96
        float v = (k < C_HID) ? W2[k*C_OUT + n] : 0.0f;
        g_cW2f[j] = f2tf32(v);
    }
}

__global__ void prep_var(const float* __restrict__ W1, const float* __restrict__ W2)
{
    int idx = blockIdx.x*blockDim.x + threadIdx.x;
    if (idx < 10752) {
        int s = idx & 1, l = (idx >> 1) & 31;
        int r = idx >> 6;
        int kt = r % 6; r /= 6;
        int nt = r % 7; int cc = r / 7;
        int gid = l >> 2, tig = l & 3;
        int k = kt*8 + tig + 4*s;                 // < 48
        int n = cc*56 + nt*8 + gid;
        float v = (n < V_HID) ? W1[k*V_HID + n] : 0.0f;
        g_vW1f[idx] = f2tf32(v);
    } else if (idx < 23296) {
        int j = idx - 10752;
        int s = j & 1, l = (j >> 1) & 31;
        int r = j >> 6;
        int ktl = r % 7; r /= 7;
        int nt = r % 7; int cc = r / 7;
        int gid = l >> 2, tig = l & 3;
        int k = cc*56 + ktl*8 + tig + 4*s;
        int n = nt*8 + gid;
        float v = (k < V_HID && n < V_OUT) ? W2[k*V_OUT + n] : 0.0f;
        g_vW2f[j] = f2tf32(v);
    }
}

// ---------------------------------------------------------------------------
// CHECK: 131072 rows. X(96)+sgn -> gelu(388) -> 96 -> *sgn -> g_Mv.
// 256 threads, 128 rows/CTA. A-in-regs, rank-1 sgn, frag-ordered weights.
// ---------------------------------------------------------------------------
#define UHS 61

__global__ __launch_bounds__(256, 1)
void check_kernel(const int* __restrict__ synd,
                  const float* __restrict__ W1raw, const float* __restrict__ B1,
                  const float* __restrict__ B2)
{
    extern __shared__ unsigned smem[];
    unsigned* sw1 = smem;                 // 5376
    unsigned* sw2 = sw1 + 5376;           // 5376
    unsigned* uh  = sw2 + 5376;           // 8*16*61 = 7808
    float* sb1  = (float*)(uh + 8*16*UHS);  // 56
    float* sw1r = sb1 + 56;                  // 56
    float* sb2  = sw1r + 56;                 // 96

    const int tid  = threadIdx.x;
    const int warp = tid >> 5, lane = tid & 31;
    const int gid  = lane >> 2, tig = lane & 3;
    const int m0   = warp * 16;
    const int base_row = blockIdx.x * 128;
    const int r0 = base_row + m0 + gid, r1 = r0 + 8;

    if (tid < 96) sb2[tid] = B2[tid];

    // A fragments for all 12 k-tiles, in registers for the whole kernel
    unsigned A[12][4];
    {
        const float* x0 = g_Mc + (size_t)r0 * 96;
        const float* x1 = g_Mc + (size_t)r1 * 96;
        #pragma unroll
        for (int kt = 0; kt < 12; kt++) {
            int c0 = kt*8 + tig;
            A[kt][0] = f2tf32(x0[c0]);
            A[kt][1] = f2tf32(x1[c0]);
            A[kt][2] = f2tf32(x0[c0+4]);
            A[kt][3] = f2tf32(x1[c0+4]);
        }
    }
    const float sg0 = 1.0f - 2.0f * (float)synd[r0];
    const float sg1 = 1.0f - 2.0f * (float)synd[r1];

    float acc2[12][4];
    #pragma unroll
    for (int n = 0; n < 12; n++)
        #pragma unroll
        for (int i = 0; i < 4; i++) acc2[n][i] = 0.0f;

    unsigned* uhw = uh + warp*16*UHS;

    for (int cc = 0; cc < 7; cc++) {
        __syncthreads();
        // stage weight chunk: pure vectorized copy
        {
            const uint4* s1 = (const uint4*)(g_cW1f + cc*5376);
            const uint4* s2 = (const uint4*)(g_cW2f + cc*5376);
            uint4* d1 = (uint4*)sw1;
            uint4* d2 = (uint4*)sw2;
            #pragma unroll
            for (int i = tid; i < 1344; i += 256) { d1[i] = s1[i]; d2[i] = s2[i]; }
            if (tid < 56) {
                int gcol = cc*56 + tid;
                bool ok = gcol < C_HID;
                sb1[tid]  = ok ? B1[gcol] : 0.0f;
                sw1r[tid] = ok ? W1raw[96*C_HID + gcol] : 0.0f;
            }
        }
        __syncthreads();

        // layer 1: init with rank-1 sgn term, then 12 k-tiles
        float acc1[7][4];
        #pragma unroll
        for (int nt = 0; nt < 7; nt++) {
            #pragma unroll
            for (int i = 0; i < 4; i++) {
                int colloc = nt*8 + 2*tig + (i & 1);
                acc1[nt][i] = ((i >> 1) ? sg1 : sg0) * sw1r[colloc];
            }
        }
        #pragma unroll
        for (int kt = 0; kt < 12; kt++) {
            #pragma unroll
            for (int nt = 0; nt < 7; nt++) {
                uint2 b = *(const uint2*)(sw1 + ((nt*12 + kt)*32 + lane)*2);
                mma_tf32(acc1[nt], A[kt], b.x, b.y);
            }
        }

        // gelu -> per-warp H (tf32)
        #pragma unroll
        for (int nt = 0; nt < 7; nt++) {
            #pragma unroll
            for (int i = 0; i < 4; i++) {
                int rowloc = gid + ((i >> 1) << 3);
                int colloc = nt*8 + 2*tig + (i & 1);
                int gcol = cc*56 + colloc;
                float h = (gcol < C_HID) ? gelu_exact(acc1[nt][i] + sb1[colloc]) : 0.0f;
                uhw[rowloc*UHS + colloc] = f2tf32(h);
            }
        }
        __syncwarp();

        // layer 2 partial over this chunk
        #pragma unroll
        for (int ktl = 0; ktl < 7; ktl++) {
            unsigned a[4];
            a[0] = uhw[gid*UHS       + ktl*8 + tig];
            a[1] = uhw[(gid+8)*UHS   + ktl*8 + tig];
            a[2] = uhw[gid*UHS       + ktl*8 + tig + 4];
            a[3] = uhw[(gid+8)*UHS   + ktl*8 + tig + 4];
            #pragma unroll
            for (int nt = 0; nt < 12; nt++) {
                uint2 b = *(const uint2*)(sw2 + ((nt*7 + ktl)*32 + lane)*2);
                mma_tf32(acc2[nt], a, b.x, b.y);
            }
        }
        __syncwarp();
    }

    // epilogue
    #pragma unroll
    for (int nt = 0; nt < 12; nt++) {
        int col = nt*8 + 2*tig;
        float bb0 = sb2[col], bb1 = sb2[col+1];
        float2 y0, y1;
        y0.x = (acc2[nt][0] + bb0) * sg0;
        y0.y = (acc2[nt][1] + bb1) * sg0;
        y1.x = (acc2[nt][2] + bb0) * sg1;
        y1.y = (acc2[nt][3] + bb1) * sg1;
        *(float2*)(g_Mv + (size_t)r0*96 + col) = y0;
        *(float2*)(g_Mv + (size_t)r1*96 + col) = y1;
    }
}

// ---------------------------------------------------------------------------
// VAR: 262144 rows. gather(48)+prior -> gelu(196) -> 48 scatter + llr.
// 256 threads, 128 rows/CTA, occupancy 2.
// ---------------------------------------------------------------------------
__global__ __launch_bounds__(256, 2)
void var_kernel(const int* __restrict__ perm,
                const float* __restrict__ prior,
                const float* __restrict__ W1raw, const float* __restrict__ B1,
                const float* __restrict__ B2,
                float* __restrict__ out_llr)
{
    extern __shared__ unsigned smem[];
    unsigned* sw1 = smem;                 // 2688
    unsigned* sw2 = sw1 + 2688;           // 3136
    unsigned* uh  = sw2 + 3136;           // 8*16*61 = 7808
    float* sb1  = (float*)(uh + 8*16*UHS);  // 56
    float* sw1r = sb1 + 56;                  // 56
    float* sb2  = sw1r + 56;                 // 49

    const int tid  = threadIdx.x;
    const int warp = tid >> 5, lane = tid & 31;
    const int gid  = lane >> 2, tig = lane & 3;
    const int m0   = warp * 16;
    const int base_row = blockIdx.x * 128;
    const int r0 = base_row + m0 + gid, r1 = r0 + 8;
    const int b0i = r0 >> 10, v0 = r0 & 1023;
    const int b1i = r1 >> 10, v1 = r1 & 1023;

    if (tid < 49) sb2[tid] = B2[tid];

    int p0[3], p1[3];
    #pragma unroll
    for (int e = 0; e < 3; e++) {
        p0[e] = perm[v0*DVd + e];
        p1[e] = perm[v1*DVd + e];
    }
    const float pr0 = prior[v0], pr1 = prior[v1];

    // A fragments (6 k-tiles = 48 cols), in registers
    unsigned A[6][4];
    {
        const float* base0 = g_Mv + (size_t)b0i*EE*DD;
        const float* base1 = g_Mv + (size_t)b1i*EE*DD;
        #pragma unroll
        for (int kt = 0; kt < 6; kt++) {
            int e = kt >> 1;
            int d = ((kt & 1) << 3) + tig;
            A[kt][0] = f2tf32(base0[p0[e]*DD + d]);
            A[kt][1] = f2tf32(base1[p1[e]*DD + d]);
            A[kt][2] = f2tf32(base0[p0[e]*DD + d + 4]);
            A[kt][3] = f2tf32(base1[p1[e]*DD + d + 4]);
        }
    }

    float acc2[7][4];
    #pragma unroll
    for (int n = 0; n < 7; n++)
        #pragma unroll
        for (int i = 0; i < 4; i++) acc2[n][i] = 0.0f;

    unsigned* uhw = uh + warp*16*UHS;

    for (int cc = 0; cc < 4; cc++) {
        __syncthreads();
        {
            const uint4* s1 = (const uint4*)(g_vW1f + cc*2688);
            const uint4* s2 = (const uint4*)(g_vW2f + cc*3136);
            uint4* d1 = (uint4*)sw1;
            uint4* d2 = (uint4*)sw2;
            #pragma unroll
            for (int i = tid; i < 784; i += 256) {
                if (i < 672) d1[i] = s1[i];
                d2[i] = s2[i];
            }
            if (tid < 56) {
                int gcol = cc*56 + tid;
                bool ok = gcol < V_HID;
                sb1[tid]  = ok ? B1[gcol] : 0.0f;
                sw1r[tid] = ok ? W1raw[48*V_HID + gcol] : 0.0f;
            }
        }
        __syncthreads();

        float acc1[7][4];
        #pragma unroll
        for (int nt = 0; nt < 7; nt++) {
            #pragma unroll
            for (int i = 0; i < 4; i++) {
                int colloc = nt*8 + 2*tig + (i & 1);
                acc1[nt][i] = ((i >> 1) ? pr1 : pr0) * sw1r[colloc];
            }
        }
        #pragma unroll
        for (int kt = 0; kt < 6; kt++) {
            #pragma unroll
            for (int nt = 0; nt < 7; nt++) {
                uint2 b = *(const uint2*)(sw1 + ((nt*6 + kt)*32 + lane)*2);
                mma_tf32(acc1[nt], A[kt], b.x, b.y);
            }
        }

        #pragma unroll
        for (int nt = 0; nt < 7; nt++) {
            #pragma unroll
            for (int i = 0; i < 4; i++) {
                int rowloc = gid + ((i >> 1) << 3);
                int colloc = nt*8 + 2*tig + (i & 1);
                int gcol = cc*56 + colloc;
                float h = (gcol < V_HID) ? gelu_exact(acc1[nt][i] + sb1[colloc]) : 0.0f;
                uhw[rowloc*UHS + colloc] = f2tf32(h);
            }
        }
        __syncwarp();

        #pragma unroll
        for (int ktl = 0; ktl < 7; ktl++) {
            unsigned a[4];
            a[0] = uhw[gid*UHS     + ktl*8 + tig];
            a[1] = uhw[(gid+8)*UHS + ktl*8 + tig];
            a[2] = uhw[gid*UHS     + ktl*8 + tig + 4];
            a[3] = uhw[(gid+8)*UHS + ktl*8 + tig + 4];
            #pragma unroll
            for (int nt = 0; nt < 7; nt++) {
                uint2 b = *(const uint2*)(sw2 + ((nt*7 + ktl)*32 + lane)*2);
                mma_tf32(acc2[nt], a, b.x, b.y);
            }
        }
        __syncwarp();
    }

    // epilogue: scatter via the same perm regs
    #pragma unroll
    for (int nt = 0; nt < 7; nt++) {
        #pragma unroll
        for (int i = 0; i < 4; i++) {
            int col = nt*8 + 2*tig + (i & 1);
            if (col > 48) continue;
            int rowsel = i >> 1;
            float y = acc2[nt][i] + sb2[col];
            if (col < 48) {
                int e = col >> 4, d = col & 15;
                int p = rowsel ? p1[e] : p0[e];
                int b = rowsel ? b1i : b0i;
                g_Mc[((size_t)b*EE + p)*DD + d] = y;
            } else {
                out_llr[rowsel ? r1 : r0] = y;
            }
        }
    }
}

// ---------------------------------------------------------------------------
extern "C" void kernel_launch(void* const* d_in, const int* in_sizes, int n_in,
                              void* d_out, int out_size)
{
    const int*   synd  = (const int*)  d_in[0];
    const float* prior = (const float*)d_in[2];
    const int*   perm  = (const int*)  d_in[3];
    const float* cW1   = (const float*)d_in[4];
    const float* cb1   = (const float*)d_in[5];
    const float* cW2   = (const float*)d_in[6];
    const float* cb2   = (const float*)d_in[7];
    const float* vW1   = (const float*)d_in[8];
    const float* vb1   = (const float*)d_in[9];
    const float* vW2   = (const float*)d_in[10];
    const float* vb2   = (const float*)d_in[11];
    float* out = (float*)d_out;

    const int T = out_size / (BATCH * NVAR);

    const int check_smem = (5376 + 5376 + 8*16*UHS) * 4 + (56+56+96)*4;
    const int var_smem   = (2688 + 3136 + 8*16*UHS) * 4 + (56+56+49)*4;

    cudaFuncSetAttribute(check_kernel, cudaFuncAttributeMaxDynamicSharedMemorySize, check_smem);
    cudaFuncSetAttribute(var_kernel,   cudaFuncAttributeMaxDynamicSharedMemorySize, var_smem);

    init_kernel<<<(BATCH*EE*DD + 255)/256, 256>>>(prior, perm);
    prep_check<<<(75264 + 255)/256, 256>>>(cW1, cW2);
    prep_var<<<(23296 + 255)/256, 256>>>(vW1, vW2);

    const int check_blocks = (BATCH*NCHK) / 128;   // 1024
    const int var_blocks   = (BATCH*NVAR) / 128;   // 2048

    for (int t = 0; t < T; t++) {
        check_kernel<<<check_blocks, 256, check_smem>>>(synd, cW1, cb1, cb2);
        var_kernel<<<var_blocks, 256, var_smem>>>(perm, prior, vW1, vb1, vb2,
                                                  out + (size_t)t * BATCH * NVAR);
    }
}

// round 5
// speedup vs baseline: 4.0359x; 1.1366x over previous
#include <cuda_runtime.h>
#include <math.h>

#define BATCH 256
#define NCHK  512
#define NVAR  1024
#define DVd   3
#define DD    16
#define EE    3072

#define C_IN   97
#define C_HID  388
#define C_OUT  96
#define V_IN   49
#define V_HID  196
#define V_OUT  49

// Persistent message buffers
__device__ float g_Mc[(size_t)BATCH*EE*DD];   // 50.3 MB
__device__ float g_Mv[(size_t)BATCH*EE*DD];   // 50.3 MB

// Fragment-ordered tf32 weight buffers (filled once per launch)
__device__ unsigned g_cW1f[7*7*12*64];        // [cc][nt][kt][lane][2]
__device__ unsigned g_cW2f[7*12*7*64];        // [cc][nt][ktl][lane][2]
__device__ unsigned g_vW1f[4*7*6*64];         // [cc][nt][kt][lane][2]
__device__ unsigned g_vW2f[4*7*7*64];         // [cc][nt][ktl][lane][2]

__device__ __forceinline__ float rcp_fast(float x){
    float r; asm("rcp.approx.f32 %0, %1;" : "=f"(r) : "f"(x)); return r;
}
// Branchless gelu: 0.5x(1+erf(x/sqrt2)), A&S 7.1.26 erf (max abs err 1.5e-7)
__device__ __forceinline__ float gelu_fast(float x){
    float z = fabsf(x) * 0.7071067811865476f;
    float t = rcp_fast(fmaf(0.3275911f, z, 1.0f));
    float p = fmaf(t, 1.061405429f, -1.453152027f);
    p = fmaf(t, p, 1.421413741f);
    p = fmaf(t, p, -0.284496736f);
    p = fmaf(t, p, 0.254829592f);
    p *= t;
    float e = __expf(-0.5f * x * x);
    float erfa = fmaf(-p, e, 1.0f);          // erf(|x|/sqrt2)
    float s = copysignf(erfa, x);
    return 0.5f * x * (1.0f + s);
}
__device__ __forceinline__ unsigned f2tf32(float x){
    unsigned r; asm("cvt.rn.tf32.f32 %0, %1;" : "=r"(r) : "f"(x)); return r;
}
__device__ __forceinline__ void mma_tf32(float* d, const unsigned* a, unsigned b0, unsigned b1){
    asm volatile("mma.sync.aligned.m16n8k8.row.col.f32.tf32.tf32.f32 "
        "{%0,%1,%2,%3},{%4,%5,%6,%7},{%8,%9},{%0,%1,%2,%3};"
        : "+f"(d[0]),"+f"(d[1]),"+f"(d[2]),"+f"(d[3])
        : "r"(a[0]),"r"(a[1]),"r"(a[2]),"r"(a[3]), "r"(b0),"r"(b1));
}

// ---------------------------------------------------------------------------
__global__ void init_kernel(const float* __restrict__ prior,
                            const int* __restrict__ perm)
{
    int idx = blockIdx.x * blockDim.x + threadIdx.x;
    if (idx >= BATCH*EE*DD) return;
    int d  = idx & (DD-1);
    int bp = idx >> 4;
    int p  = bp % EE;
    int b  = bp / EE;
    int j  = perm[p];
    float v = (d == 0) ? prior[p / DVd] : 0.0f;
    g_Mc[((size_t)b*EE + j)*DD + d] = v;
}

// ---------------------------------------------------------------------------
__global__ void prep_check(const float* __restrict__ W1, const float* __restrict__ W2)
{
    int idx = blockIdx.x*blockDim.x + threadIdx.x;
    if (idx < 37632) {
        int s = idx & 1, l = (idx >> 1) & 31;
        int r = idx >> 6;
        int kt = r % 12; r /= 12;
        int nt = r % 7;  int cc = r / 7;
        int gid = l >> 2, tig = l & 3;
        int k = kt*8 + tig + 4*s;                 // < 96
        int n = cc*56 + nt*8 + gid;
        float v = (n < C_HID) ? W1[k*C_HID + n] : 0.0f;
        g_cW1f[idx] = f2tf32(v);
    } else if (idx < 75264) {
        int j = idx - 37632;
        int s = j & 1, l = (j >> 1) & 31;
        int r = j >> 6;
        int ktl = r % 7; r /= 7;
        int nt = r % 12; int cc = r / 12;
        int gid = l >> 2, tig = l & 3;
        int k = cc*56 + ktl*8 + tig + 4*s;
        int n = nt*8 + gid;                       // < 96
        float v = (k < C_HID) ? W2[k*C_OUT + n] : 0.0f;
        g_cW2f[j] = f2tf32(v);
    }
}

__global__ void prep_var(const float* __restrict__ W1, const float* __restrict__ W2)
{
    int idx = blockIdx.x*blockDim.x + threadIdx.x;
    if (idx < 10752) {
        int s = idx & 1, l = (idx >> 1) & 31;
        int r = idx >> 6;
        int kt = r % 6; r /= 6;
        int nt = r % 7; int cc = r / 7;
        int gid = l >> 2, tig = l & 3;
        int k = kt*8 + tig + 4*s;                 // < 48
        int n = cc*56 + nt*8 + gid;
        float v = (n < V_HID) ? W1[k*V_HID + n] : 0.0f;
        g_vW1f[idx] = f2tf32(v);
    } else if (idx < 23296) {
        int j = idx - 10752;
        int s = j & 1, l = (j >> 1) & 31;
        int r = j >> 6;
        int ktl = r % 7; r /= 7;
        int nt = r % 7; int cc = r / 7;
        int gid = l >> 2, tig = l & 3;
        int k = cc*56 + ktl*8 + tig + 4*s;
        int n = nt*8 + gid;
        float v = (k < V_HID && n < V_OUT) ? W2[k*V_OUT + n] : 0.0f;
        g_vW2f[j] = f2tf32(v);
    }
}

// ---------------------------------------------------------------------------
// CHECK: 131072 rows. 256 thr (8 warps, 128 rows), 2 CTAs/SM.
// Warp-private A-frag smem + H smem; weights streamed from L1/L2 via __ldg.
// No __syncthreads after prologue.
// ---------------------------------------------------------------------------
#define UHS 61

__global__ __launch_bounds__(256, 2)
void check_kernel(const int* __restrict__ synd,
                  const float* __restrict__ W1raw, const float* __restrict__ B1,
                  const float* __restrict__ B2)
{
    extern __shared__ unsigned smem[];
    uint4*    sXf  = (uint4*)smem;                 // 8*12*32 uint4 = 48KB
    unsigned* sH   = smem + 12288;                 // 8*16*61 = 7808 words
    float*    sb1a = (float*)(sH + 8*16*UHS);      // 392
    float*    sw1r = sb1a + 392;                   // 392
    float*    sb2  = sw1r + 392;                   // 96

    const int tid  = threadIdx.x;
    const int warp = tid >> 5, lane = tid & 31;
    const int gid  = lane >> 2, tig = lane & 3;
    const int base_row = blockIdx.x * 128;
    const int r0 = base_row + warp*16 + gid, r1 = r0 + 8;

    // ---- prologue ----
    for (int i = tid; i < 392; i += 256) {
        bool ok = i < C_HID;
        sb1a[i] = ok ? B1[i] : 0.0f;
        sw1r[i] = ok ? W1raw[96*C_HID + i] : 0.0f;
    }
    if (tid < 96) sb2[tid] = B2[tid];

    {
        const float* x0 = g_Mc + (size_t)r0 * 96;
        const float* x1 = g_Mc + (size_t)r1 * 96;
        uint4* myX = sXf + warp*12*32 + lane;
        #pragma unroll
        for (int kt = 0; kt < 12; kt++) {
            int c = kt*8 + tig;
            uint4 v;
            v.x = f2tf32(x0[c]);   v.y = f2tf32(x1[c]);
            v.z = f2tf32(x0[c+4]); v.w = f2tf32(x1[c+4]);
            myX[kt*32] = v;
        }
    }
    const float sg0 = 1.0f - 2.0f * (float)synd[r0];
    const float sg1 = 1.0f - 2.0f * (float)synd[r1];
    __syncthreads();

    float acc2[12][4];
    #pragma unroll
    for (int n = 0; n < 12; n++)
        #pragma unroll
        for (int i = 0; i < 4; i++) acc2[n][i] = 0.0f;

    unsigned* sHw = sH + warp*16*UHS;
    const uint4* myX = sXf + warp*12*32 + lane;

    for (int cc = 0; cc < 7; cc++) {
        // ---- layer 1 ----
        float acc1[7][4];
        #pragma unroll
        for (int nt = 0; nt < 7; nt++) {
            #pragma unroll
            for (int i = 0; i < 4; i++) {
                int gcol = cc*56 + nt*8 + 2*tig + (i & 1);
                acc1[nt][i] = ((i >> 1) ? sg1 : sg0) * sw1r[gcol];
            }
        }
        const uint2* wp1 = (const uint2*)g_cW1f + (size_t)cc*7*12*32 + lane;
        #pragma unroll 4
        for (int kt = 0; kt < 12; kt++) {
            uint4 a4 = myX[kt*32];
            unsigned a[4] = {a4.x, a4.y, a4.z, a4.w};
            #pragma unroll
            for (int nt = 0; nt < 7; nt++) {
                uint2 b = __ldg(wp1 + (size_t)(nt*12 + kt)*32);
                mma_tf32(acc1[nt], a, b.x, b.y);
            }
        }

        // ---- gelu -> warp H (tf32); pad cols are exactly 0 ----
        #pragma unroll
        for (int nt = 0; nt < 7; nt++) {
            #pragma unroll
            for (int i = 0; i < 4; i++) {
                int rowloc = gid + ((i >> 1) << 3);
                int colloc = nt*8 + 2*tig + (i & 1);
                float h = gelu_fast(acc1[nt][i] + sb1a[cc*56 + colloc]);
                sHw[rowloc*UHS + colloc] = f2tf32(h);
            }
        }
        __syncwarp();

        // ---- layer 2 partial ----
        const uint2* wp2 = (const uint2*)g_cW2f + (size_t)cc*12*7*32 + lane;
        #pragma unroll 2
        for (int ktl = 0; ktl < 7; ktl++) {
            unsigned a[4];
            a[0] = sHw[gid*UHS     + ktl*8 + tig];
            a[1] = sHw[(gid+8)*UHS + ktl*8 + tig];
            a[2] = sHw[gid*UHS     + ktl*8 + tig + 4];
            a[3] = sHw[(gid+8)*UHS + ktl*8 + tig + 4];
            #pragma unroll
            for (int nt = 0; nt < 12; nt++) {
                uint2 b = __ldg(wp2 + (size_t)(nt*7 + ktl)*32);
                mma_tf32(acc2[nt], a, b.x, b.y);
            }
        }
        __syncwarp();
    }

    // ---- epilogue ----
    #pragma unroll
    for (int nt = 0; nt < 12; nt++) {
        int col = nt*8 + 2*tig;
        float bb0 = sb2[col], bb1 = sb2[col+1];
        float2 y0, y1;
        y0.x = (acc2[nt][0] + bb0) * sg0;
        y0.y = (acc2[nt][1] + bb1) * sg0;
        y1.x = (acc2[nt][2] + bb0) * sg1;
        y1.y = (acc2[nt][3] + bb1) * sg1;
        *(float2*)(g_Mv + (size_t)r0*96 + col) = y0;
        *(float2*)(g_Mv + (size_t)r1*96 + col) = y1;
    }
}

// ---------------------------------------------------------------------------
// VAR: 262144 rows. Same structure; gather/scatter via perm.
// ---------------------------------------------------------------------------
__global__ __launch_bounds__(256, 2)
void var_kernel(const int* __restrict__ perm,
                const float* __restrict__ prior,
                const float* __restrict__ W1raw, const float* __restrict__ B1,
                const float* __restrict__ B2,
                float* __restrict__ out_llr)
{
    extern __shared__ unsigned smem[];
    uint4*    sXf  = (uint4*)smem;                 // 8*6*32 uint4 = 24KB
    unsigned* sH   = smem + 6144;                  // 7808 words
    float*    sb1a = (float*)(sH + 8*16*UHS);      // 224
    float*    sw1r = sb1a + 224;                   // 224
    float*    sb2  = sw1r + 224;                   // 49

    const int tid  = threadIdx.x;
    const int warp = tid >> 5, lane = tid & 31;
    const int gid  = lane >> 2, tig = lane & 3;
    const int base_row = blockIdx.x * 128;
    const int r0 = base_row + warp*16 + gid, r1 = r0 + 8;
    const int b0i = r0 >> 10, v0 = r0 & 1023;
    const int b1i = r1 >> 10, v1 = r1 & 1023;

    for (int i = tid; i < 224; i += 256) {
        bool ok = i < V_HID;
        sb1a[i] = ok ? B1[i] : 0.0f;
        sw1r[i] = ok ? W1raw[48*V_HID + i] : 0.0f;
    }
    if (tid < 49) sb2[tid] = B2[tid];

    int p0[3], p1[3];
    #pragma unroll
    for (int e = 0; e < 3; e++) {
        p0[e] = perm[v0*DVd + e];
        p1[e] = perm[v1*DVd + e];
    }
    const float pr0 = prior[v0], pr1 = prior[v1];

    {
        const float* base0 = g_Mv + (size_t)b0i*EE*DD;
        const float* base1 = g_Mv + (size_t)b1i*EE*DD;
        uint4* myX = sXf + warp*6*32 + lane;
        #pragma unroll
        for (int kt = 0; kt < 6; kt++) {
            int e = kt >> 1;
            int d = ((kt & 1) << 3) + tig;
            uint4 v;
            v.x = f2tf32(base0[p0[e]*DD + d]);
            v.y = f2tf32(base1[p1[e]*DD + d]);
            v.z = f2tf32(base0[p0[e]*DD + d + 4]);
            v.w = f2tf32(base1[p1[e]*DD + d + 4]);
            myX[kt*32] = v;
        }
    }
    __syncthreads();

    float acc2[7][4];
    #pragma unroll
    for (int n = 0; n < 7; n++)
        #pragma unroll
        for (int i = 0; i < 4; i++) acc2[n][i] = 0.0f;

    unsigned* sHw = sH + warp*16*UHS;
    const uint4* myX = sXf + warp*6*32 + lane;

    for (int cc = 0; cc < 4; cc++) {
        float acc1[7][4];
        #pragma unroll
        for (int nt = 0; nt < 7; nt++) {
            #pragma unroll
            for (int i = 0; i < 4; i++) {
                int gcol = cc*56 + nt*8 + 2*tig + (i & 1);
                acc1[nt][i] = ((i >> 1) ? pr1 : pr0) * sw1r[gcol];
            }
        }
        const uint2* wp1 = (const uint2*)g_vW1f + (size_t)cc*7*6*32 + lane;
        #pragma unroll 3
        for (int kt = 0; kt < 6; kt++) {
            uint4 a4 = myX[kt*32];
            unsigned a[4] = {a4.x, a4.y, a4.z, a4.w};
            #pragma unroll
            for (int nt = 0; nt < 7; nt++) {
                uint2 b = __ldg(wp1 + (size_t)(nt*6 + kt)*32);
                mma_tf32(acc1[nt], a, b.x, b.y);
            }
        }

        #pragma unroll
        for (int nt = 0; nt < 7; nt++) {
            #pragma unroll
            for (int i = 0; i < 4; i++) {
                int rowloc = gid + ((i >> 1) << 3);
                int colloc = nt*8 + 2*tig + (i & 1);
                float h = gelu_fast(acc1[nt][i] + sb1a[cc*56 + colloc]);
                sHw[rowloc*UHS + colloc] = f2tf32(h);
            }
        }
        __syncwarp();

        const uint2* wp2 = (const uint2*)g_vW2f + (size_t)cc*7*7*32 + lane;
        #pragma unroll 2
        for (int ktl = 0; ktl < 7; ktl++) {
            unsigned a[4];
            a[0] = sHw[gid*UHS     + ktl*8 + tig];
            a[1] = sHw[(gid+8)*UHS + ktl*8 + tig];
            a[2] = sHw[gid*UHS     + ktl*8 + tig + 4];
            a[3] = sHw[(gid+8)*UHS + ktl*8 + tig + 4];
            #pragma unroll
            for (int nt = 0; nt < 7; nt++) {
                uint2 b = __ldg(wp2 + (size_t)(nt*7 + ktl)*32);
                mma_tf32(acc2[nt], a, b.x, b.y);
            }
        }
        __syncwarp();
    }

    // ---- epilogue: scatter via perm regs ----
    #pragma unroll
    for (int nt = 0; nt < 7; nt++) {
        #pragma unroll
        for (int i = 0; i < 4; i++) {
            int col = nt*8 + 2*tig + (i & 1);
            if (col > 48) continue;
            int rowsel = i >> 1;
            float y = acc2[nt][i] + sb2[col];
            if (col < 48) {
                int e = col >> 4, d = col & 15;
                int p = rowsel ? p1[e] : p0[e];
                int b = rowsel ? b1i : b0i;
                g_Mc[((size_t)b*EE + p)*DD + d] = y;
            } else {
                out_llr[rowsel ? r1 : r0] = y;
            }
        }
    }
}

// ---------------------------------------------------------------------------
extern "C" void kernel_launch(void* const* d_in, const int* in_sizes, int n_in,
                              void* d_out, int out_size)
{
    const int*   synd  = (const int*)  d_in[0];
    const float* prior = (const float*)d_in[2];
    const int*   perm  = (const int*)  d_in[3];
    const float* cW1   = (const float*)d_in[4];
    const float* cb1   = (const float*)d_in[5];
    const float* cW2   = (const float*)d_in[6];
    const float* cb2   = (const float*)d_in[7];
    const float* vW1   = (const float*)d_in[8];
    const float* vb1   = (const float*)d_in[9];
    const float* vW2   = (const float*)d_in[10];
    const float* vb2   = (const float*)d_in[11];
    float* out = (float*)d_out;

    const int T = out_size / (BATCH * NVAR);

    const int check_smem = (12288 + 8*16*UHS)*4 + (392+392+96)*4 + 64;   // ~84 KB
    const int var_smem   = (6144  + 8*16*UHS)*4 + (224+224+49)*4 + 64;   // ~58 KB

    cudaFuncSetAttribute(check_kernel, cudaFuncAttributeMaxDynamicSharedMemorySize, check_smem);
    cudaFuncSetAttribute(var_kernel,   cudaFuncAttributeMaxDynamicSharedMemorySize, var_smem);

    init_kernel<<<(BATCH*EE*DD + 255)/256, 256>>>(prior, perm);
    prep_check<<<(75264 + 255)/256, 256>>>(cW1, cW2);
    prep_var<<<(23296 + 255)/256, 256>>>(vW1, vW2);

    const int check_blocks = (BATCH*NCHK) / 128;   // 1024
    const int var_blocks   = (BATCH*NVAR) / 128;   // 2048

    for (int t = 0; t < T; t++) {
        check_kernel<<<check_blocks, 256, check_smem>>>(synd, cW1, cb1, cb2);
        var_kernel<<<var_blocks, 256, var_smem>>>(perm, prior, vW1, vb1, vb2,
                                                  out + (size_t)t * BATCH * NVAR);
    }
}